// round 12
// baseline (speedup 1.0000x reference)
#include <cuda_runtime.h>
#include <math.h>

#define BATCH 2
#define NPTS  8192
#define IC    64
#define OC    128
#define KNN   16
#define NROWS (BATCH*NPTS)      /* 16384 */
#define EPSF  1e-5f

#define GSEG  8                 /* KNN candidate segments per query */
#define SEGN  (NPTS/GSEG)       /* 1024 */
#define BCAP  40
#define BTRIG 32
#define MLP_GRID 296

typedef unsigned long long ull;

/* ---------------- scratch (no allocations allowed) ---------------- */
__device__ int   g_knn[NROWS*KNN];
__device__ float g_mid[NROWS*OC];
__device__ float g_ypre[NROWS*OC];
__device__ float g_resid[NROWS*OC];
__device__ float g_segd[GSEG*KNN*NROWS];
__device__ int   g_segi[GSEG*KNN*NROWS];
__device__ float g_part[MLP_GRID*OC*2];
__device__ float g_mu[OC];
__device__ float g_rstd[OC];

__device__ __forceinline__ float gelu_f(float x){
    return 0.5f*x*(1.0f + erff(x*0.70710678118654752440f));
}

/* ---------------- packed f32x2 helpers (PURE asm: schedulable) ---------------- */
__device__ __forceinline__ ull pk(float lo, float hi){
    ull r; asm("mov.b64 %0,{%1,%2};" : "=l"(r) : "f"(lo), "f"(hi)); return r;
}
__device__ __forceinline__ void upk(ull v, float& lo, float& hi){
    asm("mov.b64 {%0,%1},%2;" : "=f"(lo), "=f"(hi) : "l"(v));
}
__device__ __forceinline__ ull mul2(ull a, ull b){
    ull r; asm("mul.rn.f32x2 %0,%1,%2;" : "=l"(r) : "l"(a), "l"(b)); return r;
}
__device__ __forceinline__ ull add2(ull a, ull b){
    ull r; asm("add.rn.f32x2 %0,%1,%2;" : "=l"(r) : "l"(a), "l"(b)); return r;
}
__device__ __forceinline__ ull fma2(ull a, ull b, ull c){
    ull r; asm("fma.rn.f32x2 %0,%1,%2,%3;" : "=l"(r) : "l"(a), "l"(b), "l"(c)); return r;
}

/* =============== K1a: segmented KNN, SoA tile + packed distances =============== */
#define K1_THREADS 128
#define TILE_C     SEGN

#define FLUSH() do{                                                   \
    for (int t = 0; t < cnt; t++){                                    \
        float d2f = bd[t]; int jj = bi[t];                            \
        _Pragma("unroll")                                             \
        for (int s = 0; s < KNN; s++){                                \
            bool  lt = d2f < kd[s];                                   \
            float od = kd[s]; int oi = ki[s];                         \
            kd[s] = lt ? d2f : od;  ki[s] = lt ? jj : oi;             \
            d2f   = lt ? od  : d2f; jj    = lt ? oi : jj;             \
        }                                                             \
    }                                                                 \
    cnt = 0; kmax = kd[KNN-1];                                        \
}while(0)

__global__ void __launch_bounds__(K1_THREADS)
knn_seg_kernel(const float* __restrict__ pts)
{
    __shared__ __align__(16) float sXx[TILE_C];
    __shared__ __align__(16) float sYy[TILE_C];
    __shared__ __align__(16) float sZz[TILE_C];
    __shared__ __align__(16) float sWw[TILE_C];

    const int q     = blockIdx.x * K1_THREADS + threadIdx.x;
    const int seg   = blockIdx.y;
    const int cbase = (q >> 13) << 13;
    const int sbase = cbase + seg*SEGN;

    const float qx = pts[q*3+0], qy = pts[q*3+1], qz = pts[q*3+2];
    const float qs = qx*qx + qy*qy + qz*qz;

    for (int t = threadIdx.x; t < TILE_C; t += K1_THREADS){
        const int j = sbase + t;
        float x = pts[j*3+0], y = pts[j*3+1], z = pts[j*3+2];
        sXx[t] = x; sYy[t] = y; sZz[t] = z;
        sWw[t] = x*x + y*y + z*z;
    }
    __syncthreads();

    const ull* pX = reinterpret_cast<const ull*>(sXx);
    const ull* pY = reinterpret_cast<const ull*>(sYy);
    const ull* pZ = reinterpret_cast<const ull*>(sZz);
    const ull* pW = reinterpret_cast<const ull*>(sWw);

    const ull qx2 = pk(qx,qx), qy2 = pk(qy,qy), qz2 = pk(qz,qz);
    const ull qs2 = pk(qs,qs), m2  = pk(-2.0f,-2.0f);

    float kd[KNN]; int ki[KNN];
#pragma unroll
    for (int s = 0; s < KNN; s++){ kd[s] = 3.4e38f; ki[s] = cbase; }
    float bd[BCAP]; int bi[BCAP];
    int   cnt = 0;
    float kmax = 3.4e38f;

#pragma unroll 2
    for (int p = 0; p < TILE_C/2; p++){
        const ull cx = pX[p];
        const ull cy = pY[p];
        const ull cz = pZ[p];
        const ull cw = pW[p];
        /* same per-element op order as scalar version: mul, fma, fma */
        ull dot  = fma2(qz2, cz, fma2(qy2, cy, mul2(qx2, cx)));
        ull base = add2(qs2, cw);
        ull d2p  = fma2(m2, dot, base);
        float d0, d1; upk(d2p, d0, d1);
        if (d0 < kmax){ bd[cnt] = d0; bi[cnt] = sbase + 2*p;     cnt++; }
        if (d1 < kmax){ bd[cnt] = d1; bi[cnt] = sbase + 2*p + 1; cnt++; }
        if (p & 1){
            if (__any_sync(0xffffffffu, cnt >= BTRIG)) FLUSH();
        }
    }
    FLUSH();

#pragma unroll
    for (int t = 0; t < KNN; t++){
        g_segd[(seg*KNN + t)*NROWS + q] = kd[t];
        g_segi[(seg*KNN + t)*NROWS + q] = ki[t];
    }
}

/* =============== K1b: bitonic top-16 merge tree (register-only) =============== */
__device__ __forceinline__ bool lexlt(float d1, int i1, float d2, int i2){
    return (d1 < d2) || (d1 == d2 && i1 < i2);
}

__device__ __forceinline__ void mergeTop16(float* ad, int* ai,
                                           const float* bdv, const int* biv)
{
    float td[16]; int ti[16];
#pragma unroll
    for (int i = 0; i < 16; i++){
        float db = bdv[15-i]; int ib = biv[15-i];
        bool t = lexlt(db, ib, ad[i], ai[i]);
        td[i] = t ? db : ad[i];
        ti[i] = t ? ib : ai[i];
    }
#pragma unroll
    for (int k = 8; k >= 1; k >>= 1){
#pragma unroll
        for (int i = 0; i < 16; i++){
            if ((i & k) == 0){
                const int j = i + k;
                bool sw = lexlt(td[j], ti[j], td[i], ti[i]);
                float d0 = td[i]; int i0 = ti[i];
                td[i] = sw ? td[j] : d0;   ti[i] = sw ? ti[j] : i0;
                td[j] = sw ? d0 : td[j];   ti[j] = sw ? i0 : ti[j];
            }
        }
    }
#pragma unroll
    for (int i = 0; i < 16; i++){ ad[i] = td[i]; ai[i] = ti[i]; }
}

#define LOADSEG(s, D, I) do{                                  \
    _Pragma("unroll")                                         \
    for (int t = 0; t < 16; t++){                             \
        D[t] = g_segd[((s)*KNN + t)*NROWS + q];               \
        I[t] = g_segi[((s)*KNN + t)*NROWS + q];               \
    }                                                         \
}while(0)

__global__ void __launch_bounds__(256)
knn_merge_kernel(void)
{
    const int q = blockIdx.x*256 + threadIdx.x;
    float A[16], B[16], C[16], D[16];
    int   Ai[16], Bi[16], Ci[16], Di[16];

    LOADSEG(0, A, Ai); LOADSEG(1, B, Bi);
    mergeTop16(A, Ai, B, Bi);
    LOADSEG(2, B, Bi); LOADSEG(3, C, Ci);
    mergeTop16(B, Bi, C, Ci);
    mergeTop16(A, Ai, B, Bi);
    LOADSEG(4, B, Bi); LOADSEG(5, C, Ci);
    mergeTop16(B, Bi, C, Ci);
    LOADSEG(6, C, Ci); LOADSEG(7, D, Di);
    mergeTop16(C, Ci, D, Di);
    mergeTop16(B, Bi, C, Ci);
    mergeTop16(A, Ai, B, Bi);

#pragma unroll
    for (int t = 0; t < 16; t++) g_knn[q*KNN + t] = Ai[t];
}

/* ================= MLP common pieces ================= */
#define K2_THREADS 512
#define RT         16
#define NTILES     (NROWS/RT)    /* 1024 */

/* 16 warps, each warp handles one row of 128 channels */
__device__ __forceinline__ void ln_rows16(float* buf, const float* __restrict__ g,
                                          const float* __restrict__ b,
                                          const float* __restrict__ sw,
                                          const float* __restrict__ sb, int tid)
{
    const int r = tid >> 5, lane = tid & 31;
    float v0 = buf[r*128 +       lane];
    float v1 = buf[r*128 +  32 + lane];
    float v2 = buf[r*128 +  64 + lane];
    float v3 = buf[r*128 +  96 + lane];
    float s  = v0+v1+v2+v3;
    float s2 = v0*v0 + v1*v1 + v2*v2 + v3*v3;
#pragma unroll
    for (int o = 16; o > 0; o >>= 1){
        s  += __shfl_xor_sync(0xffffffffu, s,  o);
        s2 += __shfl_xor_sync(0xffffffffu, s2, o);
    }
    const float mu   = s  * (1.0f/128.0f);
    const float var  = s2 * (1.0f/128.0f) - mu*mu;
    const float rstd = rsqrtf(var + EPSF);
#pragma unroll
    for (int qq = 0; qq < 4; qq++){
        const int c = qq*32 + lane;
        float v  = (qq==0)?v0:(qq==1)?v1:(qq==2)?v2:v3;
        float nv = (v - mu)*rstd*g[c] + b[c];
        if (sw) nv = nv*sw[c] + sb[c];
        buf[r*128 + c] = nv;
    }
}

extern __shared__ float smem[];

/* packed GEMM over k for NR rows of one thread; WP: const ull* pair-interleaved,
   XP: const float* activations (rowstride mult of 4) */
#define GEMM_PACKED(WP, XP, rowstride, KDIM, NR, ACC)                          \
    _Pragma("unroll")                                                          \
    for (int k = 0; k < (KDIM); k += 4){                                       \
        const ull w01 = (WP)[((k>>1)  )*128 + o];                              \
        const ull w23 = (WP)[((k>>1)+1)*128 + o];                              \
        _Pragma("unroll")                                                      \
        for (int r = 0; r < (NR); r++){                                        \
            const ulonglong2 x = *reinterpret_cast<const ulonglong2*>(         \
                &(XP)[(rh*(NR)+r)*(rowstride) + k]);                           \
            ACC[r] = fma2(x.x, w01, ACC[r]);                                   \
            ACC[r] = fma2(x.y, w23, ACC[r]);                                   \
        }                                                                      \
    }

/* ====== K2a: gather-mean -> fc1/GELU/LN1 -> fc2/GELU/LN2·dw -> g_mid ====== */
/* smem floats: W1 8192 | W2 16384 | SX 1024 | SH 2048  = 27648 (110592 B) */
#define A_W1   0
#define A_W2   (A_W1 + 64*128)
#define A_SX   (A_W2 + 128*128)
#define A_SH   (A_SX + RT*64)
#define SMEM_A_FLOATS (A_SH + RT*128)
#define SMEM_A_BYTES  (SMEM_A_FLOATS*4)

__global__ void __launch_bounds__(K2_THREADS, 2)
mlp_a_kernel(const float* __restrict__ feats,
             const float* __restrict__ fc1_w, const float* __restrict__ fc1_b,
             const float* __restrict__ ln1_g, const float* __restrict__ ln1_b,
             const float* __restrict__ fc2_w, const float* __restrict__ fc2_b,
             const float* __restrict__ ln2_g, const float* __restrict__ ln2_b,
             const float* __restrict__ dw_w,  const float* __restrict__ dw_b)
{
    float* sx = smem + A_SX;
    float* sh = smem + A_SH;

    const int tid = threadIdx.x;
    for (int i = tid; i < 64*128; i += K2_THREADS){
        int k = i >> 7, o2 = i & 127;
        smem[A_W1 + ((k>>1)<<8) + (o2<<1) + (k&1)] = fc1_w[i];
    }
    for (int i = tid; i < 128*128; i += K2_THREADS){
        int k = i >> 7, o2 = i & 127;
        smem[A_W2 + ((k>>1)<<8) + (o2<<1) + (k&1)] = fc2_w[i];
    }
    const ull* w1p = reinterpret_cast<const ull*>(smem + A_W1);
    const ull* w2p = reinterpret_cast<const ull*>(smem + A_W2);

    const int o  = tid & 127;
    const int rh = tid >> 7;                     /* 0..3, 4 rows each */
    const float bias1 = fc1_b[o], bias2 = fc2_b[o];
    __syncthreads();

    for (int tile = blockIdx.x; tile < NTILES; tile += gridDim.x){
        /* gather + mean over 16 neighbors (256 threads) */
        if (tid < 256){
            const int r  = tid >> 4, cg = tid & 15;
            const int row = tile*RT + r;
            float4 a = make_float4(0.f,0.f,0.f,0.f);
            const int* kp = &g_knn[row*KNN];
#pragma unroll
            for (int n = 0; n < KNN; n++){
                const int gi = kp[n];
                const float4 f = *reinterpret_cast<const float4*>(&feats[gi*IC + cg*4]);
                a.x += f.x; a.y += f.y; a.z += f.z; a.w += f.w;
            }
            const float inv = 1.0f/16.0f;
            *reinterpret_cast<float4*>(&sx[r*IC + cg*4]) =
                make_float4(a.x*inv, a.y*inv, a.z*inv, a.w*inv);
        }
        __syncthreads();   /* sx ready; prev-iter sh reads complete */

        /* fc1 + GELU -> sh */
        {
            ull acc[4];
#pragma unroll
            for (int r = 0; r < 4; r++) acc[r] = pk(bias1, 0.f);
            GEMM_PACKED(w1p, sx, IC, IC, 4, acc);
#pragma unroll
            for (int r = 0; r < 4; r++){
                float lo, hi; upk(acc[r], lo, hi);
                sh[(rh*4+r)*128 + o] = gelu_f(lo + hi);
            }
        }
        __syncthreads();
        ln_rows16(sh, ln1_g, ln1_b, (const float*)0, (const float*)0, tid);
        __syncthreads();

        /* fc2 (in-place on sh: all reads into regs, sync, overwrite) */
        {
            ull acc[4];
#pragma unroll
            for (int r = 0; r < 4; r++) acc[r] = pk(bias2, 0.f);
            GEMM_PACKED(w2p, sh, 128, 128, 4, acc);
            __syncthreads();   /* everyone done reading sh */
#pragma unroll
            for (int r = 0; r < 4; r++){
                float lo, hi; upk(acc[r], lo, hi);
                sh[(rh*4+r)*128 + o] = gelu_f(lo + hi);
            }
        }
        __syncthreads();
        ln_rows16(sh, ln2_g, ln2_b, dw_w, dw_b, tid);

        /* store own-lane LN2 row values to g_mid (warp-local, no sync needed) */
        {
            const int r = tid >> 5, lane = tid & 31;
            const int row = tile*RT + r;
#pragma unroll
            for (int qq = 0; qq < 4; qq++){
                const int c = qq*32 + lane;
                g_mid[row*128 + c] = sh[r*128 + c];
            }
        }
    }
}

/* ====== K2b: pw conv (+BN stats) and proj residual ====== */
/* smem floats: PWT 16384 | PRJ 8192 | SMID 2048 | SXR 1024 = 27648 (110592 B) */
#define B_PWT  0
#define B_PRJ  (B_PWT + 128*128)
#define B_SMID (B_PRJ + 64*128)
#define B_SXR  (B_SMID + RT*128)
#define SMEM_B_FLOATS (B_SXR + RT*64)
#define SMEM_B_BYTES  (SMEM_B_FLOATS*4)

__global__ void __launch_bounds__(K2_THREADS, 2)
mlp_b_kernel(const float* __restrict__ feats,
             const float* __restrict__ pw_w,  const float* __restrict__ pw_b,
             const float* __restrict__ proj_w,const float* __restrict__ proj_b)
{
    float* smid = smem + B_SMID;
    float* sxr  = smem + B_SXR;

    const int tid = threadIdx.x;
    for (int i = tid; i < 128*128; i += K2_THREADS){
        int o2 = i >> 7, k = i & 127;            /* i = o*128 + k */
        smem[B_PWT + ((k>>1)<<8) + (o2<<1) + (k&1)] = pw_w[i];
    }
    for (int i = tid; i < 64*128; i += K2_THREADS){
        int k = i >> 7, o2 = i & 127;
        smem[B_PRJ + ((k>>1)<<8) + (o2<<1) + (k&1)] = proj_w[i];
    }
    const ull* pwp = reinterpret_cast<const ull*>(smem + B_PWT);
    const ull* pjp = reinterpret_cast<const ull*>(smem + B_PRJ);

    const int o  = tid & 127;
    const int rh = tid >> 7;
    const float biasp = pw_b[o], biasj = proj_b[o];
    float bn_s = 0.f, bn_q = 0.f;
    __syncthreads();

    for (int tile = blockIdx.x; tile < NTILES; tile += gridDim.x){
        __syncthreads();   /* protect smid/sxr reuse */
        *reinterpret_cast<float4*>(&smid[tid*4]) =
            *reinterpret_cast<const float4*>(&g_mid[tile*RT*128 + tid*4]);
        if (tid < 256)
            *reinterpret_cast<float4*>(&sxr[tid*4]) =
                *reinterpret_cast<const float4*>(&feats[tile*RT*64 + tid*4]);
        __syncthreads();

        /* pw conv -> ypre (+ BN stats) */
        {
            ull acc[4];
#pragma unroll
            for (int r = 0; r < 4; r++) acc[r] = pk(biasp, 0.f);
            GEMM_PACKED(pwp, smid, 128, 128, 4, acc);
#pragma unroll
            for (int r = 0; r < 4; r++){
                float lo, hi; upk(acc[r], lo, hi);
                const float v = lo + hi;
                g_ypre[(tile*RT + rh*4 + r)*128 + o] = v;
                bn_s += v;
                bn_q  = fmaf(v, v, bn_q);
            }
        }
        /* proj residual */
        {
            ull acc[4];
#pragma unroll
            for (int r = 0; r < 4; r++) acc[r] = pk(biasj, 0.f);
            GEMM_PACKED(pjp, sxr, IC, IC, 4, acc);
#pragma unroll
            for (int r = 0; r < 4; r++){
                float lo, hi; upk(acc[r], lo, hi);
                g_resid[(tile*RT + rh*4 + r)*128 + o] = lo + hi;
            }
        }
    }

    /* per-block BN partials (deterministic); reuse smid area (sync first) */
    __syncthreads();
    float* red = smem + B_SMID;   /* 512+512 floats fit in SMID+SXR (3072) */
    red[tid] = bn_s;
    red[512 + tid] = bn_q;
    __syncthreads();
    if (tid < 128){
        g_part[(blockIdx.x*128 + tid)*2 + 0] =
            red[tid] + red[128+tid] + red[256+tid] + red[384+tid];
        g_part[(blockIdx.x*128 + tid)*2 + 1] =
            red[512+tid] + red[640+tid] + red[768+tid] + red[896+tid];
    }
}

/* ================= K3: BN finalize — one block per channel ================= */
__global__ void __launch_bounds__(256) bnfinal_kernel(void)
{
    __shared__ float rs[256], rq[256];
    const int c = blockIdx.x, tid = threadIdx.x;
    float s = 0.f, s2 = 0.f;
    for (int b = tid; b < MLP_GRID; b += 256){
        s  += g_part[(b*128 + c)*2 + 0];
        s2 += g_part[(b*128 + c)*2 + 1];
    }
    rs[tid] = s; rq[tid] = s2;
    __syncthreads();
#pragma unroll
    for (int off = 128; off > 0; off >>= 1){
        if (tid < off){ rs[tid] += rs[tid+off]; rq[tid] += rq[tid+off]; }
        __syncthreads();
    }
    if (tid == 0){
        const float mu  = rs[0] * (1.0f/(float)NROWS);
        const float var = rq[0] * (1.0f/(float)NROWS) - mu*mu;
        g_mu[c]   = mu;
        g_rstd[c] = rsqrtf(var + EPSF);
    }
}

/* ========== K4: element-wise BN apply + GELU + residual (pure stream) ========== */
#define K4_THREADS 256
#define K4_VEC     (NROWS*OC/4)     /* 524288 float4 groups */
__global__ void __launch_bounds__(K4_THREADS)
out_elem_kernel(const float* __restrict__ bn_g, const float* __restrict__ bn_b,
                float* __restrict__ out)
{
    const int i4 = blockIdx.x*K4_THREADS + threadIdx.x;
    const int c0 = (i4*4) & 127;

    const float4 y  = *reinterpret_cast<const float4*>(&g_ypre[i4*4]);
    const float4 rr = *reinterpret_cast<const float4*>(&g_resid[i4*4]);

    const float4 mu = *reinterpret_cast<const float4*>(&g_mu[c0]);
    const float4 rs = *reinterpret_cast<const float4*>(&g_rstd[c0]);
    const float4 gg = *reinterpret_cast<const float4*>(&bn_g[c0]);
    const float4 bb = *reinterpret_cast<const float4*>(&bn_b[c0]);

    float4 r;
    r.x = gelu_f((y.x - mu.x)*rs.x*gg.x + bb.x) + rr.x;
    r.y = gelu_f((y.y - mu.y)*rs.y*gg.y + bb.y) + rr.y;
    r.z = gelu_f((y.z - mu.z)*rs.z*gg.z + bb.z) + rr.z;
    r.w = gelu_f((y.w - mu.w)*rs.w*gg.w + bb.w) + rr.w;
    *reinterpret_cast<float4*>(&out[i4*4]) = r;
}

/* ============================ launcher ============================ */
extern "C" void kernel_launch(void* const* d_in, const int* in_sizes, int n_in,
                              void* d_out, int out_size)
{
    const float* pts    = (const float*)d_in[0];
    const float* feats  = (const float*)d_in[1];
    const float* fc1_w  = (const float*)d_in[2];
    const float* fc1_b  = (const float*)d_in[3];
    const float* ln1_g  = (const float*)d_in[4];
    const float* ln1_b  = (const float*)d_in[5];
    const float* fc2_w  = (const float*)d_in[6];
    const float* fc2_b  = (const float*)d_in[7];
    const float* ln2_g  = (const float*)d_in[8];
    const float* ln2_b  = (const float*)d_in[9];
    const float* dw_w   = (const float*)d_in[10];
    const float* dw_b   = (const float*)d_in[11];
    const float* pw_w   = (const float*)d_in[12];
    const float* pw_b   = (const float*)d_in[13];
    const float* bn_g   = (const float*)d_in[14];
    const float* bn_b   = (const float*)d_in[15];
    const float* proj_w = (const float*)d_in[16];
    const float* proj_b = (const float*)d_in[17];
    float* out = (float*)d_out;

    cudaFuncSetAttribute(mlp_a_kernel, cudaFuncAttributeMaxDynamicSharedMemorySize,
                         SMEM_A_BYTES);
    cudaFuncSetAttribute(mlp_b_kernel, cudaFuncAttributeMaxDynamicSharedMemorySize,
                         SMEM_B_BYTES);

    dim3 g1(NROWS / K1_THREADS, GSEG);
    knn_seg_kernel<<<g1, K1_THREADS>>>(pts);
    knn_merge_kernel<<<NROWS/256, 256>>>();
    mlp_a_kernel<<<MLP_GRID, K2_THREADS, SMEM_A_BYTES>>>(feats,
        fc1_w, fc1_b, ln1_g, ln1_b, fc2_w, fc2_b, ln2_g, ln2_b, dw_w, dw_b);
    mlp_b_kernel<<<MLP_GRID, K2_THREADS, SMEM_B_BYTES>>>(feats,
        pw_w, pw_b, proj_w, proj_b);
    bnfinal_kernel<<<OC, 256>>>();
    out_elem_kernel<<<K4_VEC/K4_THREADS, K4_THREADS>>>(bn_g, bn_b, out);
}

// round 13
// speedup vs baseline: 1.0609x; 1.0609x over previous
#include <cuda_runtime.h>
#include <math.h>

#define BATCH 2
#define NPTS  8192
#define IC    64
#define OC    128
#define KNN   16
#define NROWS (BATCH*NPTS)      /* 16384 */
#define EPSF  1e-5f

#define GSEG  8                 /* KNN candidate segments per query */
#define SEGN  (NPTS/GSEG)       /* 1024 */
#define BCAP  40
#define BTRIG 32
#define MLP_GRID 296

typedef unsigned long long ull;

/* ---------------- scratch (no allocations allowed) ---------------- */
__device__ int   g_knn[NROWS*KNN];
__device__ float g_mid[NROWS*OC];
__device__ float g_ypre[NROWS*OC];
__device__ float g_resid[NROWS*OC];
__device__ float g_segd[GSEG*KNN*NROWS];
__device__ int   g_segi[GSEG*KNN*NROWS];
__device__ float g_part[MLP_GRID*OC*2];
__device__ float g_mu[OC];
__device__ float g_rstd[OC];

__device__ __forceinline__ float gelu_f(float x){
    return 0.5f*x*(1.0f + erff(x*0.70710678118654752440f));
}

/* ---------------- packed f32x2 helpers (PURE asm: schedulable) ---------------- */
__device__ __forceinline__ ull pk(float lo, float hi){
    ull r; asm("mov.b64 %0,{%1,%2};" : "=l"(r) : "f"(lo), "f"(hi)); return r;
}
__device__ __forceinline__ void upk(ull v, float& lo, float& hi){
    asm("mov.b64 {%0,%1},%2;" : "=f"(lo), "=f"(hi) : "l"(v));
}
__device__ __forceinline__ ull mul2(ull a, ull b){
    ull r; asm("mul.rn.f32x2 %0,%1,%2;" : "=l"(r) : "l"(a), "l"(b)); return r;
}
__device__ __forceinline__ ull add2(ull a, ull b){
    ull r; asm("add.rn.f32x2 %0,%1,%2;" : "=l"(r) : "l"(a), "l"(b)); return r;
}
__device__ __forceinline__ ull fma2(ull a, ull b, ull c){
    ull r; asm("fma.rn.f32x2 %0,%1,%2,%3;" : "=l"(r) : "l"(a), "l"(b), "l"(c)); return r;
}

/* =============== K1a: segmented KNN, packed-pair tile =============== */
#define K1_THREADS 128
#define TILE_C     SEGN

#define FLUSH() do{                                                   \
    for (int t = 0; t < cnt; t++){                                    \
        float d2f = bd[t]; int jj = bi[t];                            \
        _Pragma("unroll")                                             \
        for (int s = 0; s < KNN; s++){                                \
            bool  lt = d2f < kd[s];                                   \
            float od = kd[s]; int oi = ki[s];                         \
            kd[s] = lt ? d2f : od;  ki[s] = lt ? jj : oi;             \
            d2f   = lt ? od  : d2f; jj    = lt ? oi : jj;             \
        }                                                             \
    }                                                                 \
    cnt = 0; kmax = kd[KNN-1];                                        \
}while(0)

__global__ void __launch_bounds__(K1_THREADS)
knn_seg_kernel(const float* __restrict__ pts)
{
    /* pair-packed: sA[p] = {x0,x1,y0,y1}, sB[p] = {z0,z1,w0,w1} */
    __shared__ __align__(16) float sA[TILE_C*2];
    __shared__ __align__(16) float sB[TILE_C*2];

    const int q     = blockIdx.x * K1_THREADS + threadIdx.x;
    const int seg   = blockIdx.y;
    const int cbase = (q >> 13) << 13;
    const int sbase = cbase + seg*SEGN;

    const float qx = pts[q*3+0], qy = pts[q*3+1], qz = pts[q*3+2];
    const float qs = qx*qx + qy*qy + qz*qz;

    for (int t = threadIdx.x; t < TILE_C; t += K1_THREADS){
        const int j = sbase + t;
        float x = pts[j*3+0], y = pts[j*3+1], z = pts[j*3+2];
        const int p = t >> 1, w = t & 1;
        sA[p*4 + 0 + w] = x;
        sA[p*4 + 2 + w] = y;
        sB[p*4 + 0 + w] = z;
        sB[p*4 + 2 + w] = x*x + y*y + z*z;
    }
    __syncthreads();

    const ulonglong2* pA = reinterpret_cast<const ulonglong2*>(sA);
    const ulonglong2* pB = reinterpret_cast<const ulonglong2*>(sB);

    const ull qx2 = pk(qx,qx), qy2 = pk(qy,qy), qz2 = pk(qz,qz);
    const ull qs2 = pk(qs,qs), m2  = pk(-2.0f,-2.0f);

    float kd[KNN]; int ki[KNN];
#pragma unroll
    for (int s = 0; s < KNN; s++){ kd[s] = 3.4e38f; ki[s] = cbase; }
    float bd[BCAP]; int bi[BCAP];
    int   cnt = 0;
    float kmax = 3.4e38f;

#pragma unroll 4
    for (int p = 0; p < TILE_C/2; p++){
        const ulonglong2 xy = pA[p];     /* xy.x=(x0,x1) xy.y=(y0,y1) */
        const ulonglong2 zw = pB[p];     /* zw.x=(z0,z1) zw.y=(w0,w1) */
        /* same per-element op order as scalar version: mul, fma, fma */
        ull dot  = fma2(qz2, zw.x, fma2(qy2, xy.y, mul2(qx2, xy.x)));
        ull base = add2(qs2, zw.y);
        ull d2p  = fma2(m2, dot, base);
        float d0, d1; upk(d2p, d0, d1);
        if (d0 < kmax){ bd[cnt] = d0; bi[cnt] = sbase + 2*p;     cnt++; }
        if (d1 < kmax){ bd[cnt] = d1; bi[cnt] = sbase + 2*p + 1; cnt++; }
        if (p & 1){
            if (__any_sync(0xffffffffu, cnt >= BTRIG)) FLUSH();
        }
    }
    FLUSH();

#pragma unroll
    for (int t = 0; t < KNN; t++){
        g_segd[(seg*KNN + t)*NROWS + q] = kd[t];
        g_segi[(seg*KNN + t)*NROWS + q] = ki[t];
    }
}

/* =============== K1b: bitonic top-16 merge tree (register-only) =============== */
__device__ __forceinline__ bool lexlt(float d1, int i1, float d2, int i2){
    return (d1 < d2) || (d1 == d2 && i1 < i2);
}

__device__ __forceinline__ void mergeTop16(float* ad, int* ai,
                                           const float* bdv, const int* biv)
{
    float td[16]; int ti[16];
#pragma unroll
    for (int i = 0; i < 16; i++){
        float db = bdv[15-i]; int ib = biv[15-i];
        bool t = lexlt(db, ib, ad[i], ai[i]);
        td[i] = t ? db : ad[i];
        ti[i] = t ? ib : ai[i];
    }
#pragma unroll
    for (int k = 8; k >= 1; k >>= 1){
#pragma unroll
        for (int i = 0; i < 16; i++){
            if ((i & k) == 0){
                const int j = i + k;
                bool sw = lexlt(td[j], ti[j], td[i], ti[i]);
                float d0 = td[i]; int i0 = ti[i];
                td[i] = sw ? td[j] : d0;   ti[i] = sw ? ti[j] : i0;
                td[j] = sw ? d0 : td[j];   ti[j] = sw ? i0 : ti[j];
            }
        }
    }
#pragma unroll
    for (int i = 0; i < 16; i++){ ad[i] = td[i]; ai[i] = ti[i]; }
}

#define LOADSEG(s, D, I) do{                                  \
    _Pragma("unroll")                                         \
    for (int t = 0; t < 16; t++){                             \
        D[t] = g_segd[((s)*KNN + t)*NROWS + q];               \
        I[t] = g_segi[((s)*KNN + t)*NROWS + q];               \
    }                                                         \
}while(0)

__global__ void __launch_bounds__(256)
knn_merge_kernel(void)
{
    const int q = blockIdx.x*256 + threadIdx.x;
    float A[16], B[16], C[16], D[16];
    int   Ai[16], Bi[16], Ci[16], Di[16];

    LOADSEG(0, A, Ai); LOADSEG(1, B, Bi);
    mergeTop16(A, Ai, B, Bi);
    LOADSEG(2, B, Bi); LOADSEG(3, C, Ci);
    mergeTop16(B, Bi, C, Ci);
    mergeTop16(A, Ai, B, Bi);
    LOADSEG(4, B, Bi); LOADSEG(5, C, Ci);
    mergeTop16(B, Bi, C, Ci);
    LOADSEG(6, C, Ci); LOADSEG(7, D, Di);
    mergeTop16(C, Ci, D, Di);
    mergeTop16(B, Bi, C, Ci);
    mergeTop16(A, Ai, B, Bi);

#pragma unroll
    for (int t = 0; t < 16; t++) g_knn[q*KNN + t] = Ai[t];
}

/* ================= MLP common pieces ================= */
#define K2_THREADS 512
#define RT         16
#define NTILES     (NROWS/RT)    /* 1024 */

/* 16 warps, each warp handles one row of 128 channels */
__device__ __forceinline__ void ln_rows16(float* buf, const float* __restrict__ g,
                                          const float* __restrict__ b,
                                          const float* __restrict__ sw,
                                          const float* __restrict__ sb, int tid)
{
    const int r = tid >> 5, lane = tid & 31;
    float v0 = buf[r*128 +       lane];
    float v1 = buf[r*128 +  32 + lane];
    float v2 = buf[r*128 +  64 + lane];
    float v3 = buf[r*128 +  96 + lane];
    float s  = v0+v1+v2+v3;
    float s2 = v0*v0 + v1*v1 + v2*v2 + v3*v3;
#pragma unroll
    for (int o = 16; o > 0; o >>= 1){
        s  += __shfl_xor_sync(0xffffffffu, s,  o);
        s2 += __shfl_xor_sync(0xffffffffu, s2, o);
    }
    const float mu   = s  * (1.0f/128.0f);
    const float var  = s2 * (1.0f/128.0f) - mu*mu;
    const float rstd = rsqrtf(var + EPSF);
#pragma unroll
    for (int qq = 0; qq < 4; qq++){
        const int c = qq*32 + lane;
        float v  = (qq==0)?v0:(qq==1)?v1:(qq==2)?v2:v3;
        float nv = (v - mu)*rstd*g[c] + b[c];
        if (sw) nv = nv*sw[c] + sb[c];
        buf[r*128 + c] = nv;
    }
}

extern __shared__ float smem[];

/* 2-channel x 2-row packed GEMM.
   Thread layout: op = tid & 63 (channels 2op, 2op+1), rh = tid >> 6 (rows rh*2, rh*2+1).
   Weight ull layout: (k>>1)*128 + channel; adjacent channels = one LDS.128.
   Per k-chunk(4): 2 weight LDS.128 + 2 activation LDS.128, 8 fma2. */
#define GEMM_P22(WP, XP, rowstride, KDIM, ACC0, ACC1)                          \
    _Pragma("unroll")                                                          \
    for (int k = 0; k < (KDIM); k += 4){                                       \
        const ulonglong2 wa = *reinterpret_cast<const ulonglong2*>(            \
            &(WP)[((k>>1)  )*128 + (op<<1)]);                                  \
        const ulonglong2 wb = *reinterpret_cast<const ulonglong2*>(            \
            &(WP)[((k>>1)+1)*128 + (op<<1)]);                                  \
        _Pragma("unroll")                                                      \
        for (int r = 0; r < 2; r++){                                           \
            const ulonglong2 x = *reinterpret_cast<const ulonglong2*>(         \
                &(XP)[(rh*2+r)*(rowstride) + k]);                              \
            ACC0[r] = fma2(x.x, wa.x, ACC0[r]);                                \
            ACC0[r] = fma2(x.y, wb.x, ACC0[r]);                                \
            ACC1[r] = fma2(x.x, wa.y, ACC1[r]);                                \
            ACC1[r] = fma2(x.y, wb.y, ACC1[r]);                                \
        }                                                                      \
    }

/* ====== K2a: gather-mean -> fc1/GELU/LN1 -> fc2/GELU/LN2·dw -> g_mid ====== */
/* smem floats: W1 8192 | W2 16384 | SX 1024 | SH 2048  = 27648 (110592 B) */
#define A_W1   0
#define A_W2   (A_W1 + 64*128)
#define A_SX   (A_W2 + 128*128)
#define A_SH   (A_SX + RT*64)
#define SMEM_A_FLOATS (A_SH + RT*128)
#define SMEM_A_BYTES  (SMEM_A_FLOATS*4)

__global__ void __launch_bounds__(K2_THREADS, 2)
mlp_a_kernel(const float* __restrict__ feats,
             const float* __restrict__ fc1_w, const float* __restrict__ fc1_b,
             const float* __restrict__ ln1_g, const float* __restrict__ ln1_b,
             const float* __restrict__ fc2_w, const float* __restrict__ fc2_b,
             const float* __restrict__ ln2_g, const float* __restrict__ ln2_b,
             const float* __restrict__ dw_w,  const float* __restrict__ dw_b)
{
    float* sx = smem + A_SX;
    float* sh = smem + A_SH;

    const int tid = threadIdx.x;
    for (int i = tid; i < 64*128; i += K2_THREADS){
        int k = i >> 7, o2 = i & 127;
        smem[A_W1 + ((k>>1)<<8) + (o2<<1) + (k&1)] = fc1_w[i];
    }
    for (int i = tid; i < 128*128; i += K2_THREADS){
        int k = i >> 7, o2 = i & 127;
        smem[A_W2 + ((k>>1)<<8) + (o2<<1) + (k&1)] = fc2_w[i];
    }
    const ull* w1p = reinterpret_cast<const ull*>(smem + A_W1);
    const ull* w2p = reinterpret_cast<const ull*>(smem + A_W2);

    const int op = tid & 63;           /* channel pair */
    const int rh = tid >> 6;           /* row group 0..7, 2 rows each */
    const int c0 = op*2, c1 = op*2 + 1;
    const float b1_0 = fc1_b[c0], b1_1 = fc1_b[c1];
    const float b2_0 = fc2_b[c0], b2_1 = fc2_b[c1];
    __syncthreads();

    for (int tile = blockIdx.x; tile < NTILES; tile += gridDim.x){
        /* gather + mean over 16 neighbors (256 threads) */
        if (tid < 256){
            const int r  = tid >> 4, cg = tid & 15;
            const int row = tile*RT + r;
            float4 a = make_float4(0.f,0.f,0.f,0.f);
            const int* kp = &g_knn[row*KNN];
#pragma unroll
            for (int n = 0; n < KNN; n++){
                const int gi = kp[n];
                const float4 f = *reinterpret_cast<const float4*>(&feats[gi*IC + cg*4]);
                a.x += f.x; a.y += f.y; a.z += f.z; a.w += f.w;
            }
            const float inv = 1.0f/16.0f;
            *reinterpret_cast<float4*>(&sx[r*IC + cg*4]) =
                make_float4(a.x*inv, a.y*inv, a.z*inv, a.w*inv);
        }
        __syncthreads();

        /* fc1 + GELU -> sh */
        {
            ull a0[2], a1[2];
#pragma unroll
            for (int r = 0; r < 2; r++){ a0[r] = pk(b1_0, 0.f); a1[r] = pk(b1_1, 0.f); }
            GEMM_P22(w1p, sx, IC, IC, a0, a1);
#pragma unroll
            for (int r = 0; r < 2; r++){
                float lo, hi; upk(a0[r], lo, hi);
                float l1, h1; upk(a1[r], l1, h1);
                *reinterpret_cast<float2*>(&sh[(rh*2+r)*128 + c0]) =
                    make_float2(gelu_f(lo+hi), gelu_f(l1+h1));
            }
        }
        __syncthreads();
        ln_rows16(sh, ln1_g, ln1_b, (const float*)0, (const float*)0, tid);
        __syncthreads();

        /* fc2 (in-place on sh: all reads into regs, sync, overwrite) */
        {
            ull a0[2], a1[2];
#pragma unroll
            for (int r = 0; r < 2; r++){ a0[r] = pk(b2_0, 0.f); a1[r] = pk(b2_1, 0.f); }
            GEMM_P22(w2p, sh, 128, 128, a0, a1);
            __syncthreads();   /* everyone done reading sh */
#pragma unroll
            for (int r = 0; r < 2; r++){
                float lo, hi; upk(a0[r], lo, hi);
                float l1, h1; upk(a1[r], l1, h1);
                *reinterpret_cast<float2*>(&sh[(rh*2+r)*128 + c0]) =
                    make_float2(gelu_f(lo+hi), gelu_f(l1+h1));
            }
        }
        __syncthreads();
        ln_rows16(sh, ln2_g, ln2_b, dw_w, dw_b, tid);

        /* store own-lane LN2 row values to g_mid (warp-local, no sync needed) */
        {
            const int r = tid >> 5, lane = tid & 31;
            const int row = tile*RT + r;
#pragma unroll
            for (int qq = 0; qq < 4; qq++){
                const int c = qq*32 + lane;
                g_mid[row*128 + c] = sh[r*128 + c];
            }
        }
    }
}

/* ====== K2b: pw conv (+BN stats) and proj residual ====== */
/* smem floats: PWT 16384 | PRJ 8192 | SMID 2048 | SXR 1024 = 27648 (110592 B) */
#define B_PWT  0
#define B_PRJ  (B_PWT + 128*128)
#define B_SMID (B_PRJ + 64*128)
#define B_SXR  (B_SMID + RT*128)
#define SMEM_B_FLOATS (B_SXR + RT*64)
#define SMEM_B_BYTES  (SMEM_B_FLOATS*4)

__global__ void __launch_bounds__(K2_THREADS, 2)
mlp_b_kernel(const float* __restrict__ feats,
             const float* __restrict__ pw_w,  const float* __restrict__ pw_b,
             const float* __restrict__ proj_w,const float* __restrict__ proj_b)
{
    float* smid = smem + B_SMID;
    float* sxr  = smem + B_SXR;

    const int tid = threadIdx.x;
    for (int i = tid; i < 128*128; i += K2_THREADS){
        int o2 = i >> 7, k = i & 127;            /* i = o*128 + k */
        smem[B_PWT + ((k>>1)<<8) + (o2<<1) + (k&1)] = pw_w[i];
    }
    for (int i = tid; i < 64*128; i += K2_THREADS){
        int k = i >> 7, o2 = i & 127;
        smem[B_PRJ + ((k>>1)<<8) + (o2<<1) + (k&1)] = proj_w[i];
    }
    const ull* pwp = reinterpret_cast<const ull*>(smem + B_PWT);
    const ull* pjp = reinterpret_cast<const ull*>(smem + B_PRJ);

    const int op = tid & 63;
    const int rh = tid >> 6;
    const int c0 = op*2, c1 = op*2 + 1;
    const float bp_0 = pw_b[c0], bp_1 = pw_b[c1];
    const float bj_0 = proj_b[c0], bj_1 = proj_b[c1];
    float bn_s0 = 0.f, bn_q0 = 0.f, bn_s1 = 0.f, bn_q1 = 0.f;
    __syncthreads();

    for (int tile = blockIdx.x; tile < NTILES; tile += gridDim.x){
        __syncthreads();   /* protect smid/sxr reuse */
        *reinterpret_cast<float4*>(&smid[tid*4]) =
            *reinterpret_cast<const float4*>(&g_mid[tile*RT*128 + tid*4]);
        if (tid < 256)
            *reinterpret_cast<float4*>(&sxr[tid*4]) =
                *reinterpret_cast<const float4*>(&feats[tile*RT*64 + tid*4]);
        __syncthreads();

        /* pw conv -> ypre (+ BN stats) */
        {
            ull a0[2], a1[2];
#pragma unroll
            for (int r = 0; r < 2; r++){ a0[r] = pk(bp_0, 0.f); a1[r] = pk(bp_1, 0.f); }
            GEMM_P22(pwp, smid, 128, 128, a0, a1);
#pragma unroll
            for (int r = 0; r < 2; r++){
                float lo, hi; upk(a0[r], lo, hi);
                float l1, h1; upk(a1[r], l1, h1);
                const float v0 = lo + hi, v1 = l1 + h1;
                *reinterpret_cast<float2*>(
                    &g_ypre[(tile*RT + rh*2 + r)*128 + c0]) = make_float2(v0, v1);
                bn_s0 += v0; bn_q0 = fmaf(v0, v0, bn_q0);
                bn_s1 += v1; bn_q1 = fmaf(v1, v1, bn_q1);
            }
        }
        /* proj residual */
        {
            ull a0[2], a1[2];
#pragma unroll
            for (int r = 0; r < 2; r++){ a0[r] = pk(bj_0, 0.f); a1[r] = pk(bj_1, 0.f); }
            GEMM_P22(pjp, sxr, IC, IC, a0, a1);
#pragma unroll
            for (int r = 0; r < 2; r++){
                float lo, hi; upk(a0[r], lo, hi);
                float l1, h1; upk(a1[r], l1, h1);
                *reinterpret_cast<float2*>(
                    &g_resid[(tile*RT + rh*2 + r)*128 + c0]) =
                    make_float2(lo + hi, l1 + h1);
            }
        }
    }

    /* per-block BN partials (deterministic): red_s[rh*128 + c], red_q likewise */
    __syncthreads();
    float* red_s = smem + B_PRJ;               /* reuse: 1024 floats */
    float* red_q = smem + B_PRJ + 1024;        /* 1024 floats */
    *reinterpret_cast<float2*>(&red_s[rh*128 + c0]) = make_float2(bn_s0, bn_s1);
    *reinterpret_cast<float2*>(&red_q[rh*128 + c0]) = make_float2(bn_q0, bn_q1);
    __syncthreads();
    if (tid < 128){
        float s = 0.f, q2 = 0.f;
#pragma unroll
        for (int g = 0; g < 8; g++){
            s  += red_s[g*128 + tid];
            q2 += red_q[g*128 + tid];
        }
        g_part[(blockIdx.x*128 + tid)*2 + 0] = s;
        g_part[(blockIdx.x*128 + tid)*2 + 1] = q2;
    }
}

/* ================= K3: BN finalize — one block per channel ================= */
__global__ void __launch_bounds__(256) bnfinal_kernel(void)
{
    __shared__ float rs[256], rq[256];
    const int c = blockIdx.x, tid = threadIdx.x;
    float s = 0.f, s2 = 0.f;
    for (int b = tid; b < MLP_GRID; b += 256){
        s  += g_part[(b*128 + c)*2 + 0];
        s2 += g_part[(b*128 + c)*2 + 1];
    }
    rs[tid] = s; rq[tid] = s2;
    __syncthreads();
#pragma unroll
    for (int off = 128; off > 0; off >>= 1){
        if (tid < off){ rs[tid] += rs[tid+off]; rq[tid] += rq[tid+off]; }
        __syncthreads();
    }
    if (tid == 0){
        const float mu  = rs[0] * (1.0f/(float)NROWS);
        const float var = rq[0] * (1.0f/(float)NROWS) - mu*mu;
        g_mu[c]   = mu;
        g_rstd[c] = rsqrtf(var + EPSF);
    }
}

/* ========== K4: element-wise BN apply + GELU + residual (pure stream) ========== */
#define K4_THREADS 256
#define K4_VEC     (NROWS*OC/4)     /* 524288 float4 groups */
__global__ void __launch_bounds__(K4_THREADS)
out_elem_kernel(const float* __restrict__ bn_g, const float* __restrict__ bn_b,
                float* __restrict__ out)
{
    const int i4 = blockIdx.x*K4_THREADS + threadIdx.x;
    const int c0 = (i4*4) & 127;

    const float4 y  = *reinterpret_cast<const float4*>(&g_ypre[i4*4]);
    const float4 rr = *reinterpret_cast<const float4*>(&g_resid[i4*4]);

    const float4 mu = *reinterpret_cast<const float4*>(&g_mu[c0]);
    const float4 rs = *reinterpret_cast<const float4*>(&g_rstd[c0]);
    const float4 gg = *reinterpret_cast<const float4*>(&bn_g[c0]);
    const float4 bb = *reinterpret_cast<const float4*>(&bn_b[c0]);

    float4 r;
    r.x = gelu_f((y.x - mu.x)*rs.x*gg.x + bb.x) + rr.x;
    r.y = gelu_f((y.y - mu.y)*rs.y*gg.y + bb.y) + rr.y;
    r.z = gelu_f((y.z - mu.z)*rs.z*gg.z + bb.z) + rr.z;
    r.w = gelu_f((y.w - mu.w)*rs.w*gg.w + bb.w) + rr.w;
    *reinterpret_cast<float4*>(&out[i4*4]) = r;
}

/* ============================ launcher ============================ */
extern "C" void kernel_launch(void* const* d_in, const int* in_sizes, int n_in,
                              void* d_out, int out_size)
{
    const float* pts    = (const float*)d_in[0];
    const float* feats  = (const float*)d_in[1];
    const float* fc1_w  = (const float*)d_in[2];
    const float* fc1_b  = (const float*)d_in[3];
    const float* ln1_g  = (const float*)d_in[4];
    const float* ln1_b  = (const float*)d_in[5];
    const float* fc2_w  = (const float*)d_in[6];
    const float* fc2_b  = (const float*)d_in[7];
    const float* ln2_g  = (const float*)d_in[8];
    const float* ln2_b  = (const float*)d_in[9];
    const float* dw_w   = (const float*)d_in[10];
    const float* dw_b   = (const float*)d_in[11];
    const float* pw_w   = (const float*)d_in[12];
    const float* pw_b   = (const float*)d_in[13];
    const float* bn_g   = (const float*)d_in[14];
    const float* bn_b   = (const float*)d_in[15];
    const float* proj_w = (const float*)d_in[16];
    const float* proj_b = (const float*)d_in[17];
    float* out = (float*)d_out;

    cudaFuncSetAttribute(mlp_a_kernel, cudaFuncAttributeMaxDynamicSharedMemorySize,
                         SMEM_A_BYTES);
    cudaFuncSetAttribute(mlp_b_kernel, cudaFuncAttributeMaxDynamicSharedMemorySize,
                         SMEM_B_BYTES);

    dim3 g1(NROWS / K1_THREADS, GSEG);
    knn_seg_kernel<<<g1, K1_THREADS>>>(pts);
    knn_merge_kernel<<<NROWS/256, 256>>>();
    mlp_a_kernel<<<MLP_GRID, K2_THREADS, SMEM_A_BYTES>>>(feats,
        fc1_w, fc1_b, ln1_g, ln1_b, fc2_w, fc2_b, ln2_g, ln2_b, dw_w, dw_b);
    mlp_b_kernel<<<MLP_GRID, K2_THREADS, SMEM_B_BYTES>>>(feats,
        pw_w, pw_b, proj_w, proj_b);
    bnfinal_kernel<<<OC, 256>>>();
    out_elem_kernel<<<K4_VEC/K4_THREADS, K4_THREADS>>>(bn_g, bn_b, out);
}